// round 17
// baseline (speedup 1.0000x reference)
#include <cuda_runtime.h>
#include <cuda_fp16.h>
#include <cstdint>

#define D_DIM 1024
#define M_DIM 1024
#define N_MAX 16384

#define BM 128
#define BN 128
#define BK 64                       // halves per k-tile = 128 bytes/row
#define STAGES 3
#define NPASS 3
#define TOT_TILES (NPASS * (D_DIM / BK))    // 48

#define STAGE_BYTES (BM * 128 + BN * 128)   // 32 KB (A then B)
#define SMEM_DYN_BYTES (STAGES * STAGE_BYTES)   // 96 KB -> 2 CTA/SM

// ---------------- static device scratch (no allocation allowed) -------------
__device__ __align__(16) float  g_p2[M_DIM];
__device__ __align__(16) __half g_qhi[(size_t)N_MAX * D_DIM];
__device__ __align__(16) __half g_qlo[(size_t)N_MAX * D_DIM];
__device__ __align__(16) __half g_phi[(size_t)M_DIM * D_DIM];
__device__ __align__(16) __half g_plo[(size_t)M_DIM * D_DIM];
__device__ unsigned g_cnt[N_MAX / BM];   // zero-init; finisher resets -> replay-safe

// ---------------- helpers ----------------------------------------------------
__device__ __forceinline__ uint32_t smem_to_u32(const void* p) {
    uint32_t a;
    asm("{ .reg .u64 t; cvta.to.shared.u64 t, %1; cvt.u32.u64 %0, t; }" : "=r"(a) : "l"(p));
    return a;
}

__device__ __forceinline__ void cp_async16(uint32_t dst, const void* src) {
    asm volatile("cp.async.cg.shared.global [%0], [%1], 16;" :: "r"(dst), "l"(src) : "memory");
}
#define CP_COMMIT() asm volatile("cp.async.commit_group;" ::: "memory")
#define CP_WAIT(n)  asm volatile("cp.async.wait_group %0;" :: "n"(n) : "memory")

__device__ __forceinline__ void ldsm_x4(uint32_t* r, uint32_t addr) {
    asm volatile("ldmatrix.sync.aligned.m8n8.x4.shared.b16 {%0,%1,%2,%3}, [%4];"
                 : "=r"(r[0]), "=r"(r[1]), "=r"(r[2]), "=r"(r[3]) : "r"(addr));
}

__device__ __forceinline__ void mma16816(float* c, const uint32_t* a, const uint32_t* b) {
    asm volatile(
        "mma.sync.aligned.m16n8k16.row.col.f32.f16.f16.f32 "
        "{%0,%1,%2,%3}, {%4,%5,%6,%7}, {%8,%9}, {%0,%1,%2,%3};"
        : "+f"(c[0]), "+f"(c[1]), "+f"(c[2]), "+f"(c[3])
        : "r"(a[0]), "r"(a[1]), "r"(a[2]), "r"(a[3]), "r"(b[0]), "r"(b[1]));
}

// ---------------------------------------------------------------------------
// Kernel A: split fp32 -> (hi, lo) fp16 pairs for Q and P; fused p2 for P.
// ---------------------------------------------------------------------------
__global__ __launch_bounds__(256) void convert_kernel(const float* __restrict__ q,
                                                      const float* __restrict__ p, int nq) {
    const int row  = blockIdx.x * 8 + (threadIdx.x >> 5);
    const int lane = threadIdx.x & 31;
    const bool isQ = row < nq;
    const float* src = isQ ? (q + (size_t)row * D_DIM) : (p + (size_t)(row - nq) * D_DIM);
    __half* dhi = isQ ? (g_qhi + (size_t)row * D_DIM) : (g_phi + (size_t)(row - nq) * D_DIM);
    __half* dlo = isQ ? (g_qlo + (size_t)row * D_DIM) : (g_plo + (size_t)(row - nq) * D_DIM);

    float s = 0.0f;
    #pragma unroll
    for (int hf = 0; hf < 2; hf++) {
        float4 v[4];
        #pragma unroll
        for (int g = 0; g < 2; g++) {
            const int idx = (hf * 2 + g) * 256 + lane * 8;
            v[2 * g + 0] = __ldcg(reinterpret_cast<const float4*>(src + idx));
            v[2 * g + 1] = __ldcg(reinterpret_cast<const float4*>(src + idx + 4));
        }
        #pragma unroll
        for (int g = 0; g < 2; g++) {
            const int idx = (hf * 2 + g) * 256 + lane * 8;
            const float* f = reinterpret_cast<const float*>(&v[2 * g]);
            __half h[8], l[8];
            #pragma unroll
            for (int e = 0; e < 8; e++) {
                h[e] = __float2half_rn(f[e]);
                l[e] = __float2half_rn(f[e] - __half2float(h[e]));
            }
            __stcg(reinterpret_cast<uint4*>(dhi + idx), *reinterpret_cast<const uint4*>(h));
            __stcg(reinterpret_cast<uint4*>(dlo + idx), *reinterpret_cast<const uint4*>(l));
        }
        #pragma unroll
        for (int j = 0; j < 4; j++)
            s += v[j].x * v[j].x + v[j].y * v[j].y + v[j].z * v[j].z + v[j].w * v[j].w;
    }

    if (!isQ) {                                 // fused p2 (exact fp32)
        #pragma unroll
        for (int o = 16; o; o >>= 1) s += __shfl_xor_sync(0xffffffffu, s, o);
        if (lane == 0) g_p2[row - nq] = s;
    }
}

// ---------------------------------------------------------------------------
// Kernel B: HMMA GEMM (frozen R8/R11 mainloop) + counter-gated tail softmax.
// DO NOT reorder wait/barrier: cp.async completion is per-thread; CP_WAIT
// must precede __syncthreads to make other threads' loads visible.
// Tail: last CTA of each 128-row block softmaxes those rows in place, using
// the (now dead) pipeline smem as the row cache -> ~25 live regs, no spills.
// ---------------------------------------------------------------------------
struct LoadSlots { uint32_t dst[4]; int src[4]; };

__device__ __forceinline__ void load_tile(int t, uint32_t smem0,
                                          const __half* const* passA,
                                          const __half* const* passB,
                                          const LoadSlots& ls) {
    const int stage = t % STAGES;
    const __half* A = passA[t >> 4] + (t & 15) * BK;
    const __half* B = passB[t >> 4] + (t & 15) * BK;
    const uint32_t sa = smem0 + stage * STAGE_BYTES;
    const uint32_t sb = sa + BM * 128;
    #pragma unroll
    for (int i = 0; i < 4; i++) cp_async16(sa + ls.dst[i], A + ls.src[i]);
    #pragma unroll
    for (int i = 0; i < 4; i++) cp_async16(sb + ls.dst[i], B + ls.src[i]);
}

__global__ __launch_bounds__(256, 2) void gemm_kernel(float* __restrict__ out) {
    extern __shared__ __align__(128) char dsm[];
    __shared__ unsigned s_old;
    const int tid  = threadIdx.x;
    const int lane = tid & 31;
    const int wid  = tid >> 5;
    const int wm   = wid & 1;       // 2 warps along M
    const int wn   = wid >> 1;      // 4 warps along N
    const int brow = blockIdx.y * BM;
    const int bcol = blockIdx.x * BN;

    const uint32_t smem0 = smem_to_u32(dsm);

    LoadSlots ls;
    #pragma unroll
    for (int i = 0; i < 4; i++) {
        int idx = i * 256 + tid, r = idx >> 3, c = idx & 7;
        uint32_t off = (uint32_t)(r * 128 + c * 16);
        ls.dst[i] = off ^ ((off >> 3) & 0x70);
        ls.src[i] = r * D_DIM + c * 8;
    }

    const __half* passA[NPASS] = {g_qhi + (size_t)brow * D_DIM,
                                  g_qhi + (size_t)brow * D_DIM,
                                  g_qlo + (size_t)brow * D_DIM};
    const __half* passB[NPASS] = {g_phi + (size_t)bcol * D_DIM,
                                  g_plo + (size_t)bcol * D_DIM,
                                  g_phi + (size_t)bcol * D_DIM};

    // ldmatrix per-thread addressing (XOR-swizzled 128B rows).
    const int a_row  = wm * 64 + (lane & 15);
    const uint32_t a_base = (uint32_t)(a_row * 128);
    const uint32_t a_xor  = (uint32_t)((a_row & 7) << 4);
    const uint32_t a_sel  = (lane & 16) ? 16u : 0u;
    const int b_row  = wn * 32 + (lane & 7) + ((lane & 16) ? 8 : 0);
    const uint32_t b_base = (uint32_t)(BM * 128 + b_row * 128);
    const uint32_t b_xor  = (uint32_t)((b_row & 7) << 4);
    const uint32_t b_sel  = (lane & 8) ? 16u : 0u;

    float acc[4][4][4];
    #pragma unroll
    for (int i = 0; i < 4; i++)
        #pragma unroll
        for (int j = 0; j < 4; j++)
            #pragma unroll
            for (int k = 0; k < 4; k++) acc[i][j][k] = 0.0f;

    #pragma unroll
    for (int t = 0; t < STAGES - 1; t++) {
        load_tile(t, smem0, passA, passB, ls);
        CP_COMMIT();
    }

    for (int t = 0; t < TOT_TILES; t++) {
        CP_WAIT(STAGES - 2);        // own loads for tile t done...
        __syncthreads();            // ...and everyone else's (visibility fence)
        if (t + STAGES - 1 < TOT_TILES)
            load_tile(t + STAGES - 1, smem0, passA, passB, ls);
        CP_COMMIT();

        const uint32_t sbase = smem0 + (t % STAGES) * STAGE_BYTES;
        #pragma unroll
        for (int ks = 0; ks < BK / 16; ks++) {
            uint32_t af[4][4], bf[2][4];
            #pragma unroll
            for (int mi = 0; mi < 4; mi++)
                ldsm_x4(af[mi], sbase + a_base + mi * 16 * 128 +
                                ((ks * 32 + a_sel) ^ a_xor));
            #pragma unroll
            for (int ni = 0; ni < 2; ni++)
                ldsm_x4(bf[ni], sbase + b_base + ni * 16 * 128 +
                                ((ks * 32 + b_sel) ^ b_xor));
            #pragma unroll
            for (int mi = 0; mi < 4; mi++)
                #pragma unroll
                for (int nj = 0; nj < 4; nj++)
                    mma16816(acc[mi][nj], af[mi], &bf[nj >> 1][(nj & 1) * 2]);
        }
    }

    // Epilogue: store raw qp streaming (re-read below via __ldcg only).
    #pragma unroll
    for (int mi = 0; mi < 4; mi++) {
        #pragma unroll
        for (int nj = 0; nj < 4; nj++) {
            const int r = brow + wm * 64 + mi * 16 + (lane >> 2);
            const int c = bcol + wn * 32 + nj * 8 + (lane & 3) * 2;
            __stcg(reinterpret_cast<float2*>(out + (size_t)r * M_DIM + c),
                   make_float2(acc[mi][nj][0], acc[mi][nj][1]));
            __stcg(reinterpret_cast<float2*>(out + (size_t)(r + 8) * M_DIM + c),
                   make_float2(acc[mi][nj][2], acc[mi][nj][3]));
        }
    }

    // --- completion counter: last CTA of this 128-row block runs softmax ---
    __threadfence();                    // release: tile stores before atomic
    __syncthreads();
    if (tid == 0) s_old = atomicAdd(&g_cnt[blockIdx.y], 1u);
    __syncthreads();
    if (s_old != (gridDim.x - 1)) return;

    __threadfence();                    // acquire: peers' stores now visible

    // Tail softmax: warp w handles rows [brow + w*16, +16). Pipeline smem is
    // dead -> reuse as per-warp 4KB row cache (each warp private, no barriers).
    float4* cache = reinterpret_cast<float4*>(dsm + wid * 4096);
    const float4* pp = reinterpret_cast<const float4*>(g_p2);
    #pragma unroll 1
    for (int r = 0; r < 16; r++) {
        const int row = brow + wid * 16 + r;
        float4* prow = reinterpret_cast<float4*>(out + (size_t)row * M_DIM);

        float m = -3.4e38f, sum = 0.0f;
        #pragma unroll
        for (int j = 0; j < 8; j++) {
            float4 v = __ldcg(&prow[lane + 32 * j]);    // L2-hot logits
            float4 q = pp[lane + 32 * j];
            float4 sv;
            sv.x = 2.0f * v.x - q.x;  sv.y = 2.0f * v.y - q.y;
            sv.z = 2.0f * v.z - q.z;  sv.w = 2.0f * v.w - q.w;
            cache[lane + 32 * j] = sv;
            float m4 = fmaxf(fmaxf(sv.x, sv.y), fmaxf(sv.z, sv.w));
            float mn = fmaxf(m, m4);
            sum = sum * __expf(m - mn)
                + __expf(sv.x - mn) + __expf(sv.y - mn)
                + __expf(sv.z - mn) + __expf(sv.w - mn);
            m = mn;
        }
        #pragma unroll
        for (int o = 16; o; o >>= 1) {
            float mo = __shfl_xor_sync(0xffffffffu, m, o);
            float so = __shfl_xor_sync(0xffffffffu, sum, o);
            float mn = fmaxf(m, mo);
            sum = sum * __expf(m - mn) + so * __expf(mo - mn);
            m = mn;
        }
        const float inv = 1.0f / sum;

        #pragma unroll
        for (int j = 0; j < 8; j++) {
            float4 sv = cache[lane + 32 * j];
            float4 rr;
            rr.x = __expf(sv.x - m) * inv;
            rr.y = __expf(sv.y - m) * inv;
            rr.z = __expf(sv.z - m) * inv;
            rr.w = __expf(sv.w - m) * inv;
            prow[lane + 32 * j] = rr;
        }
    }

    __syncthreads();
    if (tid == 0) g_cnt[blockIdx.y] = 0;   // reset for next graph replay
}

// ---------------------------------------------------------------------------
extern "C" void kernel_launch(void* const* d_in, const int* in_sizes, int n_in,
                              void* d_out, int out_size) {
    const float* query = (const float*)d_in[0];   // [N, 1024] fp32
    const float* proto = (const float*)d_in[1];   // [1024, 1024] fp32
    float* out = (float*)d_out;                   // [N, 1024] fp32
    const int N = in_sizes[0] / D_DIM;

    cudaFuncSetAttribute(gemm_kernel, cudaFuncAttributeMaxDynamicSharedMemorySize,
                         SMEM_DYN_BYTES);

    convert_kernel<<<(N + M_DIM) / 8, 256>>>(query, proto, N);

    dim3 grid(M_DIM / BN, N / BM);                // (8, 128)
    gemm_kernel<<<grid, 256, SMEM_DYN_BYTES>>>(out);
}